// round 1
// baseline (speedup 1.0000x reference)
#include <cuda_runtime.h>
#include <cuda_bf16.h>

// C[i, j] = sum_k |boxes[i,k] - tpts[j,k]|  -  sigmoid(logits[i, labels[j]])
// i in [0, NR), j in [0, NC). Output row-major [NR, NC].
//
// Tile: block = (32, 8) threads. Block covers 8 rows x 128 cols.
// Each thread writes one float4 (4 consecutive j). Shared caches the
// 128-col target tile (float4 pts + int label).

#define TJ 128   // cols per block
#define TR 8     // rows per block

__global__ __launch_bounds__(256) void matcher_cost_kernel(
    const float* __restrict__ logits,  // [NR, 2]
    const float* __restrict__ boxes,   // [NR, 4]
    const float* __restrict__ tpts,    // [NC, 4]
    const int*   __restrict__ tlab,    // [NC]
    float*       __restrict__ out,     // [NR, NC]
    int NR, int NC)
{
    __shared__ float4 s_t[TJ];
    __shared__ int    s_id[TJ];

    const int tx  = threadIdx.x;            // 0..31 (j-groups of 4)
    const int ty  = threadIdx.y;            // 0..7  (rows)
    const int tid = ty * 32 + tx;           // 0..255

    const int j_base = blockIdx.x * TJ;     // first col of tile
    const int i      = blockIdx.y * TR + ty;

    // Stage target tile into shared (first 128 threads).
    if (tid < TJ) {
        int j = j_base + tid;
        if (j < NC) {
            s_t[tid]  = reinterpret_cast<const float4*>(tpts)[j];
            s_id[tid] = tlab[j];
        } else {
            s_t[tid]  = make_float4(0.f, 0.f, 0.f, 0.f);
            s_id[tid] = 0;
        }
    }
    __syncthreads();

    if (i >= NR) return;

    // Per-row data (L2-resident: tiny inputs reused across all j-tiles).
    const float4 p  = reinterpret_cast<const float4*>(boxes)[i];
    const float2 lg = reinterpret_cast<const float2*>(logits)[i];
    const float prob0 = 1.0f / (1.0f + __expf(-lg.x));
    const float prob1 = 1.0f / (1.0f + __expf(-lg.y));

    const int jg = tx * 4;                  // offset of this thread's 4 cols in tile
    const int j0 = j_base + jg;
    if (j0 + 3 >= NC) {
        // Scalar tail (only if NC not multiple of 128; not hit for this shape).
        for (int k = 0; k < 4; ++k) {
            int j = j0 + k;
            if (j >= NC) break;
            float4 t = s_t[jg + k];
            float l1 = fabsf(p.x - t.x) + fabsf(p.y - t.y)
                     + fabsf(p.z - t.z) + fabsf(p.w - t.w);
            float pr = s_id[jg + k] ? prob1 : prob0;
            out[(size_t)i * NC + j] = l1 - pr;
        }
        return;
    }

    float4 r;
    {
        float4 t = s_t[jg + 0];
        r.x = fabsf(p.x - t.x) + fabsf(p.y - t.y) + fabsf(p.z - t.z) + fabsf(p.w - t.w)
            - (s_id[jg + 0] ? prob1 : prob0);
    }
    {
        float4 t = s_t[jg + 1];
        r.y = fabsf(p.x - t.x) + fabsf(p.y - t.y) + fabsf(p.z - t.z) + fabsf(p.w - t.w)
            - (s_id[jg + 1] ? prob1 : prob0);
    }
    {
        float4 t = s_t[jg + 2];
        r.z = fabsf(p.x - t.x) + fabsf(p.y - t.y) + fabsf(p.z - t.z) + fabsf(p.w - t.w)
            - (s_id[jg + 2] ? prob1 : prob0);
    }
    {
        float4 t = s_t[jg + 3];
        r.w = fabsf(p.x - t.x) + fabsf(p.y - t.y) + fabsf(p.z - t.z) + fabsf(p.w - t.w)
            - (s_id[jg + 3] ? prob1 : prob0);
    }

    reinterpret_cast<float4*>(out + (size_t)i * NC)[tx + blockIdx.x * (TJ / 4)] = r;
}

extern "C" void kernel_launch(void* const* d_in, const int* in_sizes, int n_in,
                              void* d_out, int out_size)
{
    // Inputs (metadata order):
    //   0: pred_logits  [bs, Q, 2]      float32
    //   1: pred_boxes   [bs, Q, 4]      float32
    //   2: tgt_pts      [bs, T, 2, 2]   float32
    //   3: tgt_labels   [bs, T]         int32
    const float* logits = (const float*)d_in[0];
    const float* boxes  = (const float*)d_in[1];
    const float* tpts   = (const float*)d_in[2];
    const int*   tlab   = (const int*)d_in[3];
    float* out = (float*)d_out;

    const int NR = in_sizes[1] / 4;   // bs*Q rows (boxes: 4 floats each)
    const int NC = in_sizes[3];       // bs*T cols (labels: 1 int each)

    dim3 block(32, 8);
    dim3 grid((NC + TJ - 1) / TJ, (NR + TR - 1) / TR);
    matcher_cost_kernel<<<grid, block>>>(logits, boxes, tpts, tlab, out, NR, NC);
}

// round 2
// speedup vs baseline: 2.8588x; 2.8588x over previous
#include <cuda_runtime.h>
#include <cuda_bf16.h>

// C[i, j] = sum_k |boxes[i,k] - tpts[j,k]|  -  sigmoid(logits[i, labels[j]])
// i in [0, NR=8192), j in [0, NC=4096). Output row-major [NR, NC] fp32 (128 MB).
//
// Strategy: HBM-store-bound kernel. No shared memory. Each thread owns 8
// columns (two float4 groups: targets live in registers, loaded once), loops
// over RPB rows. Row data (box + negated sigmoid probs) is a uniform LDG
// broadcast. Sigmoids precomputed by a tiny pre-pass into __device__ scratch.

#define RPB 32          // rows per block
#define TPB 128         // threads per block; block covers 128*8 = 1024 columns

__device__ float2 g_nprobs[65536];   // negated sigmoid(logits), [NR] float2

__global__ __launch_bounds__(256) void prob_kernel(
    const float* __restrict__ logits, int NR)
{
    int i = blockIdx.x * blockDim.x + threadIdx.x;
    if (i < NR) {
        float2 lg = reinterpret_cast<const float2*>(logits)[i];
        float2 np;
        np.x = -1.0f / (1.0f + __expf(-lg.x));
        np.y = -1.0f / (1.0f + __expf(-lg.y));
        g_nprobs[i] = np;
    }
}

__device__ __forceinline__ float l1_4(float4 p, float4 t) {
    return fabsf(p.x - t.x) + fabsf(p.y - t.y)
         + fabsf(p.z - t.z) + fabsf(p.w - t.w);
}

__global__ __launch_bounds__(TPB) void cost_kernel(
    const float* __restrict__ boxes,   // [NR, 4]
    const float* __restrict__ tpts,    // [NC, 4]
    const int*   __restrict__ tlab,    // [NC]
    float*       __restrict__ out,     // [NR, NC]
    int NR, int NC)
{
    const int NC4 = NC >> 2;                         // float4 groups per row
    const int gA  = blockIdx.x * (2 * TPB) + threadIdx.x;   // group A
    const int gB  = gA + TPB;                                // group B
    const int i0  = blockIdx.y * RPB;

    if (4 * gA + 3 >= NC) return;                    // not hit for NC=4096
    const bool haveB = (4 * gB + 3 < NC);

    const float4* tpts4  = reinterpret_cast<const float4*>(tpts);
    const float4* boxes4 = reinterpret_cast<const float4*>(boxes);

    // Register-cached targets: 8 columns per thread.
    const float4 a0 = tpts4[4 * gA + 0];
    const float4 a1 = tpts4[4 * gA + 1];
    const float4 a2 = tpts4[4 * gA + 2];
    const float4 a3 = tpts4[4 * gA + 3];
    const bool sa0 = tlab[4 * gA + 0] != 0;
    const bool sa1 = tlab[4 * gA + 1] != 0;
    const bool sa2 = tlab[4 * gA + 2] != 0;
    const bool sa3 = tlab[4 * gA + 3] != 0;

    float4 b0, b1, b2, b3;
    bool sb0 = false, sb1 = false, sb2 = false, sb3 = false;
    if (haveB) {
        b0 = tpts4[4 * gB + 0];
        b1 = tpts4[4 * gB + 1];
        b2 = tpts4[4 * gB + 2];
        b3 = tpts4[4 * gB + 3];
        sb0 = tlab[4 * gB + 0] != 0;
        sb1 = tlab[4 * gB + 1] != 0;
        sb2 = tlab[4 * gB + 2] != 0;
        sb3 = tlab[4 * gB + 3] != 0;
    }

    const int rmax = min(RPB, NR - i0);

    #pragma unroll 4
    for (int r = 0; r < rmax; ++r) {
        const int i = i0 + r;
        const float4 p  = boxes4[i];          // uniform across block -> broadcast
        const float2 np = g_nprobs[i];        // negated sigmoids, uniform

        float4 oA;
        oA.x = l1_4(p, a0) + (sa0 ? np.y : np.x);
        oA.y = l1_4(p, a1) + (sa1 ? np.y : np.x);
        oA.z = l1_4(p, a2) + (sa2 ? np.y : np.x);
        oA.w = l1_4(p, a3) + (sa3 ? np.y : np.x);

        float4* orow = reinterpret_cast<float4*>(out) + (size_t)i * NC4;
        orow[gA] = oA;

        if (haveB) {
            float4 oB;
            oB.x = l1_4(p, b0) + (sb0 ? np.y : np.x);
            oB.y = l1_4(p, b1) + (sb1 ? np.y : np.x);
            oB.z = l1_4(p, b2) + (sb2 ? np.y : np.x);
            oB.w = l1_4(p, b3) + (sb3 ? np.y : np.x);
            orow[gB] = oB;
        }
    }
}

extern "C" void kernel_launch(void* const* d_in, const int* in_sizes, int n_in,
                              void* d_out, int out_size)
{
    // Inputs (metadata order):
    //   0: pred_logits  [bs, Q, 2]      float32
    //   1: pred_boxes   [bs, Q, 4]      float32
    //   2: tgt_pts      [bs, T, 2, 2]   float32
    //   3: tgt_labels   [bs, T]         int32
    const float* logits = (const float*)d_in[0];
    const float* boxes  = (const float*)d_in[1];
    const float* tpts   = (const float*)d_in[2];
    const int*   tlab   = (const int*)d_in[3];
    float* out = (float*)d_out;

    const int NR = in_sizes[1] / 4;   // bs*Q
    const int NC = in_sizes[3];       // bs*T

    prob_kernel<<<(NR + 255) / 256, 256>>>(logits, NR);

    const int cols_per_block = 2 * TPB * 4;   // 1024 columns
    dim3 grid((NC + cols_per_block - 1) / cols_per_block,
              (NR + RPB - 1) / RPB);
    cost_kernel<<<grid, TPB>>>(boxes, tpts, tlab, out, NR, NC);
}

// round 3
// speedup vs baseline: 3.2161x; 1.1250x over previous
#include <cuda_runtime.h>
#include <cuda_bf16.h>

// C[i, j] = sum_k |boxes[i,k] - tpts[j,k]|  -  sigmoid(logits[i, labels[j]])
// NR = bs*Q = 8192 rows, NC = bs*T = 4096 cols. Output row-major fp32 (128 MB).
//
// Single fused kernel, HBM-store-bound design:
//  - Each thread owns 8 columns (2 float4 target groups, register-cached once).
//  - Block covers 1024 cols x 32 rows. Per-block row stage (box float4 +
//    negated sigmoid probs float2) computed by first 32 threads into 768 B
//    of shared; hot loop reads uniform broadcast LDS (no L2 latency exposed).
//  - Streaming float4 stores (evict-first): output is write-once.

#define RPB 32          // rows per block
#define TPB 128         // threads per block; block covers 128*8 = 1024 columns

__device__ __forceinline__ float l1_4(float4 p, float4 t) {
    return fabsf(p.x - t.x) + fabsf(p.y - t.y)
         + fabsf(p.z - t.z) + fabsf(p.w - t.w);
}

__global__ __launch_bounds__(TPB) void cost_kernel(
    const float* __restrict__ logits,  // [NR, 2]
    const float* __restrict__ boxes,   // [NR, 4]
    const float* __restrict__ tpts,    // [NC, 4]
    const int*   __restrict__ tlab,    // [NC]
    float*       __restrict__ out,     // [NR, NC]
    int NR, int NC)
{
    __shared__ float4 s_box[RPB];
    __shared__ float2 s_np[RPB];

    const int NC4 = NC >> 2;
    const int gA  = blockIdx.x * (2 * TPB) + threadIdx.x;   // float4 group A
    const int gB  = gA + TPB;                                // float4 group B
    const int i0  = blockIdx.y * RPB;

    // Stage row data: first 32 threads each handle one row.
    if (threadIdx.x < RPB) {
        int i = i0 + threadIdx.x;
        if (i < NR) {
            s_box[threadIdx.x] = reinterpret_cast<const float4*>(boxes)[i];
            float2 lg = reinterpret_cast<const float2*>(logits)[i];
            float2 np;
            np.x = -1.0f / (1.0f + __expf(-lg.x));
            np.y = -1.0f / (1.0f + __expf(-lg.y));
            s_np[threadIdx.x] = np;
        }
    }

    const float4* tpts4 = reinterpret_cast<const float4*>(tpts);

    // Register-cached targets: 8 columns per thread (loaded while staging).
    float4 a0, a1, a2, a3, b0, b1, b2, b3;
    bool sa0 = false, sa1 = false, sa2 = false, sa3 = false;
    bool sb0 = false, sb1 = false, sb2 = false, sb3 = false;
    const bool haveA = (4 * gA + 3 < NC);
    const bool haveB = (4 * gB + 3 < NC);
    if (haveA) {
        a0 = tpts4[4 * gA + 0];  a1 = tpts4[4 * gA + 1];
        a2 = tpts4[4 * gA + 2];  a3 = tpts4[4 * gA + 3];
        sa0 = tlab[4 * gA + 0] != 0;  sa1 = tlab[4 * gA + 1] != 0;
        sa2 = tlab[4 * gA + 2] != 0;  sa3 = tlab[4 * gA + 3] != 0;
    }
    if (haveB) {
        b0 = tpts4[4 * gB + 0];  b1 = tpts4[4 * gB + 1];
        b2 = tpts4[4 * gB + 2];  b3 = tpts4[4 * gB + 3];
        sb0 = tlab[4 * gB + 0] != 0;  sb1 = tlab[4 * gB + 1] != 0;
        sb2 = tlab[4 * gB + 2] != 0;  sb3 = tlab[4 * gB + 3] != 0;
    }

    __syncthreads();

    if (!haveA) return;

    const int rmax = min(RPB, NR - i0);

    #pragma unroll 4
    for (int r = 0; r < rmax; ++r) {
        const int i = i0 + r;
        const float4 p  = s_box[r];   // broadcast LDS, conflict-free
        const float2 np = s_np[r];

        float4 oA;
        oA.x = l1_4(p, a0) + (sa0 ? np.y : np.x);
        oA.y = l1_4(p, a1) + (sa1 ? np.y : np.x);
        oA.z = l1_4(p, a2) + (sa2 ? np.y : np.x);
        oA.w = l1_4(p, a3) + (sa3 ? np.y : np.x);

        float4* orow = reinterpret_cast<float4*>(out) + (size_t)i * NC4;
        __stcs(orow + gA, oA);

        if (haveB) {
            float4 oB;
            oB.x = l1_4(p, b0) + (sb0 ? np.y : np.x);
            oB.y = l1_4(p, b1) + (sb1 ? np.y : np.x);
            oB.z = l1_4(p, b2) + (sb2 ? np.y : np.x);
            oB.w = l1_4(p, b3) + (sb3 ? np.y : np.x);
            __stcs(orow + gB, oB);
        }
    }
}

extern "C" void kernel_launch(void* const* d_in, const int* in_sizes, int n_in,
                              void* d_out, int out_size)
{
    // Inputs (metadata order):
    //   0: pred_logits  [bs, Q, 2]      float32
    //   1: pred_boxes   [bs, Q, 4]      float32
    //   2: tgt_pts      [bs, T, 2, 2]   float32
    //   3: tgt_labels   [bs, T]         int32
    const float* logits = (const float*)d_in[0];
    const float* boxes  = (const float*)d_in[1];
    const float* tpts   = (const float*)d_in[2];
    const int*   tlab   = (const int*)d_in[3];
    float* out = (float*)d_out;

    const int NR = in_sizes[1] / 4;   // bs*Q
    const int NC = in_sizes[3];       // bs*T

    const int cols_per_block = 2 * TPB * 4;   // 1024 columns
    dim3 grid((NC + cols_per_block - 1) / cols_per_block,
              (NR + RPB - 1) / RPB);
    cost_kernel<<<grid, TPB>>>(logits, boxes, tpts, tlab, out, NR, NC);
}